// round 5
// baseline (speedup 1.0000x reference)
#include <cuda_runtime.h>

// B_Splines fused, barrier-free: out[i][j] = spline(x[i];coefs) * spline(t[j];coefs_2)
// degree P=3, N_COEFS=128, knots[132] open-uniform on [0,1], h = 1/125.
//
// Single DRAM-write-bound kernel, 64-row x 1024-col tiles, grid = 1024 CTAs.
// Every warp is self-sufficient: each lane evaluates 2 row-splines (rows
// r0+lane, r0+lane+32) and its 4 column-splines; the store drain broadcasts
// row values via __shfl_sync. No __syncthreads, no SMEM -> warps begin
// storing as soon as their own ~6 cheap division-free evals finish.
//
// Inputs (metadata order): x[8192], t[8192], knots[132], coefs[128], coefs_2[128]
// Output: float32 [8192, 8192]

#define NX 8192
#define NT 8192

#define TPB 256
#define ROWS_PER_BLOCK 64
#define COLS_PER_BLOCK (TPB * 4)   // 1024

__device__ __forceinline__ int clampi(int i) {
    return min(max(i, 3), 128);
}

// reciprocal of (n * h), n in {1,2,3}, h = 1/125 (open-uniform closed form)
__device__ __forceinline__ float recip_n(int n) {
    return n == 1 ? 125.0f : (n == 2 ? 62.5f : 41.666668f);
}

__device__ __forceinline__ float rden(int k, int a, int b) {
    return recip_n(clampi(k + a) - clampi(k + b));
}

__device__ __forceinline__ float spline_eval(float xv,
                                             const float* __restrict__ knots,
                                             const float* __restrict__ c) {
    // Knot span: uniform interior gives the guess; local fix against actual
    // fp32 knots keeps indicator parity (t[k] <= x < t[k+1]).
    int k = 3 + (int)floorf(xv * 125.0f);
    k = max(3, min(127, k));
    while (k > 3   && xv <  __ldg(knots + k))     k--;
    while (k < 127 && xv >= __ldg(knots + k + 1)) k++;

    float tm2 = __ldg(knots + k - 2);
    float tm1 = __ldg(knots + k - 1);
    float t0  = __ldg(knots + k);
    float t1  = __ldg(knots + k + 1);
    float t2  = __ldg(knots + k + 2);
    float t3  = __ldg(knots + k + 3);

    float l1 = xv - t0,  r1 = t1 - xv;
    float l2 = xv - tm1, r2 = t2 - xv;
    float l3 = xv - tm2, r3 = t3 - xv;

    // Triangular algorithm (NURBS A2.2), closed-form denominators.
    float N0, N1, N2, N3, temp, saved;
    temp = rden(k, 1, 0);
    N1 = l1 * temp;
    N0 = r1 * temp;
    temp  = N0 * rden(k, 1, -1);
    N0    = r1 * temp;
    saved = l2 * temp;
    temp  = N1 * rden(k, 2, 0);
    N1    = saved + r2 * temp;
    N2    = l1 * temp;
    temp  = N0 * rden(k, 1, -2);
    N0    = r1 * temp;
    saved = l3 * temp;
    temp  = N1 * rden(k, 2, -1);
    N1    = saved + r2 * temp;
    saved = l2 * temp;
    temp  = N2 * rden(k, 3, 0);
    N2    = saved + r3 * temp;
    N3    = l1 * temp;

    return __ldg(c + k - 3) * N0 + __ldg(c + k - 2) * N1 +
           __ldg(c + k - 1) * N2 + __ldg(c + k)     * N3;
}

__global__ __launch_bounds__(TPB) void bspline_outer_fused(
    const float* __restrict__ x,
    const float* __restrict__ t,
    const float* __restrict__ knots,
    const float* __restrict__ coefs,
    const float* __restrict__ coefs2,
    float* __restrict__ out) {
    const int tid  = threadIdx.x;
    const int lane = tid & 31;
    const int j    = blockIdx.x * COLS_PER_BLOCK + tid * 4;  // base column
    const int r0   = blockIdx.y * ROWS_PER_BLOCK;            // base row

    // Per-lane row spline values: rows r0+lane and r0+lane+32.
    float v0 = spline_eval(__ldg(x + r0 + lane),      knots, coefs);
    float v1 = spline_eval(__ldg(x + r0 + lane + 32), knots, coefs);

    // Column spline values for this thread's 4 columns (independent -> ILP).
    float4 tv = *reinterpret_cast<const float4*>(t + j);
    float4 s4;
    s4.x = spline_eval(tv.x, knots, coefs2);
    s4.y = spline_eval(tv.y, knots, coefs2);
    s4.z = spline_eval(tv.z, knots, coefs2);
    s4.w = spline_eval(tv.w, knots, coefs2);

    // Store drain: 64 rows x 16B per thread, fully coalesced. Row values come
    // from warp shuffles -> no barrier, no SMEM.
    float4* outp = reinterpret_cast<float4*>(out + (size_t)r0 * NT + j);
#pragma unroll 8
    for (int r = 0; r < 32; r++) {
        float a = __shfl_sync(0xFFFFFFFFu, v0, r);
        float4 o;
        o.x = a * s4.x;
        o.y = a * s4.y;
        o.z = a * s4.z;
        o.w = a * s4.w;
        *outp = o;
        outp += NT / 4;
    }
#pragma unroll 8
    for (int r = 0; r < 32; r++) {
        float a = __shfl_sync(0xFFFFFFFFu, v1, r);
        float4 o;
        o.x = a * s4.x;
        o.y = a * s4.y;
        o.z = a * s4.z;
        o.w = a * s4.w;
        *outp = o;
        outp += NT / 4;
    }
}

extern "C" void kernel_launch(void* const* d_in, const int* in_sizes, int n_in,
                              void* d_out, int out_size) {
    const float* x      = (const float*)d_in[0];
    const float* t      = (const float*)d_in[1];
    const float* knots  = (const float*)d_in[2];
    const float* coefs  = (const float*)d_in[3];
    const float* coefs2 = (const float*)d_in[4];
    float* out = (float*)d_out;

    dim3 grid(NT / COLS_PER_BLOCK, NX / ROWS_PER_BLOCK);  // (8, 128)
    bspline_outer_fused<<<grid, TPB>>>(x, t, knots, coefs, coefs2, out);
}

// round 6
// speedup vs baseline: 1.0058x; 1.0058x over previous
#include <cuda_runtime.h>

// B_Splines fused: out[i][j] = spline(x[i]; coefs) * spline(t[j]; coefs_2)
// degree P=3, N_COEFS=128, knots[132] open-uniform on [0,1], h = 1/125.
//
// Single DRAM-write-bound kernel. Tile = 32 rows x 2048 cols, grid = 1024
// CTAs (one full wave). Each thread owns TWO float4 column groups -> two
// independent coalesced STG.128 per row iteration (deeper store pipelining,
// half the loop overhead). Output is write-once -> __stcs (evict-streaming)
// to keep it from thrashing L2 (measured ~0.8us win in R2 vs R4/R5).
// Division-free Cox-de Boor: open-uniform knots make every denominator n*h,
// n in {1,2,3}, via integer clamps -> constant-select reciprocal.
//
// Inputs (metadata order): x[8192], t[8192], knots[132], coefs[128], coefs_2[128]
// Output: float32 [8192, 8192]

#define NX 8192
#define NT 8192

#define TPB 256
#define ROWS_PER_BLOCK 32
#define COLS_PER_BLOCK 2048   // two 1024-wide groups

__device__ __forceinline__ int clampi(int i) {
    return min(max(i, 3), 128);
}

// reciprocal of (n * h), n in {1,2,3}, h = 1/125 (open-uniform closed form)
__device__ __forceinline__ float recip_n(int n) {
    return n == 1 ? 125.0f : (n == 2 ? 62.5f : 41.666668f);
}

__device__ __forceinline__ float rden(int k, int a, int b) {
    return recip_n(clampi(k + a) - clampi(k + b));
}

__device__ __forceinline__ float spline_eval(float xv,
                                             const float* __restrict__ knots,
                                             const float* __restrict__ c) {
    // Knot span: uniform interior gives the guess; local fix against actual
    // fp32 knots keeps indicator parity (t[k] <= x < t[k+1]).
    int k = 3 + (int)floorf(xv * 125.0f);
    k = max(3, min(127, k));
    while (k > 3   && xv <  __ldg(knots + k))     k--;
    while (k < 127 && xv >= __ldg(knots + k + 1)) k++;

    float tm2 = __ldg(knots + k - 2);
    float tm1 = __ldg(knots + k - 1);
    float t0  = __ldg(knots + k);
    float t1  = __ldg(knots + k + 1);
    float t2  = __ldg(knots + k + 2);
    float t3  = __ldg(knots + k + 3);

    float l1 = xv - t0,  r1 = t1 - xv;
    float l2 = xv - tm1, r2 = t2 - xv;
    float l3 = xv - tm2, r3 = t3 - xv;

    // Triangular algorithm (NURBS A2.2), closed-form denominators.
    float N0, N1, N2, N3, temp, saved;
    temp = rden(k, 1, 0);
    N1 = l1 * temp;
    N0 = r1 * temp;
    temp  = N0 * rden(k, 1, -1);
    N0    = r1 * temp;
    saved = l2 * temp;
    temp  = N1 * rden(k, 2, 0);
    N1    = saved + r2 * temp;
    N2    = l1 * temp;
    temp  = N0 * rden(k, 1, -2);
    N0    = r1 * temp;
    saved = l3 * temp;
    temp  = N1 * rden(k, 2, -1);
    N1    = saved + r2 * temp;
    saved = l2 * temp;
    temp  = N2 * rden(k, 3, 0);
    N2    = saved + r3 * temp;
    N3    = l1 * temp;

    return __ldg(c + k - 3) * N0 + __ldg(c + k - 2) * N1 +
           __ldg(c + k - 1) * N2 + __ldg(c + k)     * N3;
}

__global__ __launch_bounds__(TPB) void bspline_outer_fused(
    const float* __restrict__ x,
    const float* __restrict__ t,
    const float* __restrict__ knots,
    const float* __restrict__ coefs,
    const float* __restrict__ coefs2,
    float* __restrict__ out) {
    __shared__ float s_sx[ROWS_PER_BLOCK];

    const int tid = threadIdx.x;
    const int j0  = blockIdx.x * COLS_PER_BLOCK + tid * 4;   // group A column
    const int j1  = j0 + TPB * 4;                            // group B column
    const int r0  = blockIdx.y * ROWS_PER_BLOCK;             // base row

    // Row spline values -> SMEM (threads 0..31).
    if (tid < ROWS_PER_BLOCK) {
        s_sx[tid] = spline_eval(__ldg(x + r0 + tid), knots, coefs);
    }

    // Column spline values for this thread's 8 columns (independent -> ILP).
    float4 tva = *reinterpret_cast<const float4*>(t + j0);
    float4 tvb = *reinterpret_cast<const float4*>(t + j1);
    float4 sa, sb;
    sa.x = spline_eval(tva.x, knots, coefs2);
    sa.y = spline_eval(tva.y, knots, coefs2);
    sa.z = spline_eval(tva.z, knots, coefs2);
    sa.w = spline_eval(tva.w, knots, coefs2);
    sb.x = spline_eval(tvb.x, knots, coefs2);
    sb.y = spline_eval(tvb.y, knots, coefs2);
    sb.z = spline_eval(tvb.z, knots, coefs2);
    sb.w = spline_eval(tvb.w, knots, coefs2);

    __syncthreads();

    // Store drain: 32 rows x 2 coalesced STG.128 per thread per row.
    float4* pa = reinterpret_cast<float4*>(out + (size_t)r0 * NT + j0);
    float4* pb = reinterpret_cast<float4*>(out + (size_t)r0 * NT + j1);
#pragma unroll 8
    for (int r = 0; r < ROWS_PER_BLOCK; r++) {
        float a = s_sx[r];
        float4 oa, ob;
        oa.x = a * sa.x; oa.y = a * sa.y; oa.z = a * sa.z; oa.w = a * sa.w;
        ob.x = a * sb.x; ob.y = a * sb.y; ob.z = a * sb.z; ob.w = a * sb.w;
        __stcs(pa, oa);
        __stcs(pb, ob);
        pa += NT / 4;
        pb += NT / 4;
    }
}

extern "C" void kernel_launch(void* const* d_in, const int* in_sizes, int n_in,
                              void* d_out, int out_size) {
    const float* x      = (const float*)d_in[0];
    const float* t      = (const float*)d_in[1];
    const float* knots  = (const float*)d_in[2];
    const float* coefs  = (const float*)d_in[3];
    const float* coefs2 = (const float*)d_in[4];
    float* out = (float*)d_out;

    dim3 grid(NT / COLS_PER_BLOCK, NX / ROWS_PER_BLOCK);  // (4, 256) = 1024 CTAs
    bspline_outer_fused<<<grid, TPB>>>(x, t, knots, coefs, coefs2, out);
}

// round 7
// speedup vs baseline: 1.0150x; 1.0091x over previous
#include <cuda_runtime.h>

// B_Splines fused: out[i][j] = spline(x[i]; coefs) * spline(t[j]; coefs_2)
// degree P=3, N_COEFS=128, knots[132] open-uniform on [0,1], h = 1/125.
//
// Consolidated best-measured config across 6 rounds:
//  - single fused kernel, 64-row x 1024-col tiles, grid = 1024 CTAs
//    (one full resident wave at 8 CTAs/SM; every other tile shape measured worse)
//  - SMEM row cache + one barrier (>= shuffle variant)
//  - __stcs streaming stores (write-once 256MB output; worth ~0.5-0.8us)
//  - division-free Cox-de Boor prologue: open-uniform knots make every
//    denominator n*h, n in {1,2,3}, via integer clamps -> constant-select
//    reciprocal (no MUFU burst at CTA start)
// Kernel is pinned at the DRAM write-cycle ceiling (~5.2 TB/s effective);
// L2 sits at ~50%, issue ~20% -> no non-memory lever remains.
//
// Inputs (metadata order): x[8192], t[8192], knots[132], coefs[128], coefs_2[128]
// Output: float32 [8192, 8192]

#define NX 8192
#define NT 8192

#define TPB 256
#define ROWS_PER_BLOCK 64
#define COLS_PER_BLOCK (TPB * 4)   // 1024

__device__ __forceinline__ int clampi(int i) {
    return min(max(i, 3), 128);
}

// reciprocal of (n * h), n in {1,2,3}, h = 1/125 (open-uniform closed form)
__device__ __forceinline__ float recip_n(int n) {
    return n == 1 ? 125.0f : (n == 2 ? 62.5f : 41.666668f);
}

__device__ __forceinline__ float rden(int k, int a, int b) {
    return recip_n(clampi(k + a) - clampi(k + b));
}

__device__ __forceinline__ float spline_eval(float xv,
                                             const float* __restrict__ knots,
                                             const float* __restrict__ c) {
    // Knot span: uniform interior gives the guess; local fix against actual
    // fp32 knots keeps indicator parity (t[k] <= x < t[k+1]).
    int k = 3 + (int)floorf(xv * 125.0f);
    k = max(3, min(127, k));
    while (k > 3   && xv <  __ldg(knots + k))     k--;
    while (k < 127 && xv >= __ldg(knots + k + 1)) k++;

    float tm2 = __ldg(knots + k - 2);
    float tm1 = __ldg(knots + k - 1);
    float t0  = __ldg(knots + k);
    float t1  = __ldg(knots + k + 1);
    float t2  = __ldg(knots + k + 2);
    float t3  = __ldg(knots + k + 3);

    float l1 = xv - t0,  r1 = t1 - xv;
    float l2 = xv - tm1, r2 = t2 - xv;
    float l3 = xv - tm2, r3 = t3 - xv;

    // Triangular algorithm (NURBS A2.2), closed-form denominators.
    float N0, N1, N2, N3, temp, saved;
    temp = rden(k, 1, 0);
    N1 = l1 * temp;
    N0 = r1 * temp;
    temp  = N0 * rden(k, 1, -1);
    N0    = r1 * temp;
    saved = l2 * temp;
    temp  = N1 * rden(k, 2, 0);
    N1    = saved + r2 * temp;
    N2    = l1 * temp;
    temp  = N0 * rden(k, 1, -2);
    N0    = r1 * temp;
    saved = l3 * temp;
    temp  = N1 * rden(k, 2, -1);
    N1    = saved + r2 * temp;
    saved = l2 * temp;
    temp  = N2 * rden(k, 3, 0);
    N2    = saved + r3 * temp;
    N3    = l1 * temp;

    return __ldg(c + k - 3) * N0 + __ldg(c + k - 2) * N1 +
           __ldg(c + k - 1) * N2 + __ldg(c + k)     * N3;
}

__global__ __launch_bounds__(TPB, 8) void bspline_outer_fused(
    const float* __restrict__ x,
    const float* __restrict__ t,
    const float* __restrict__ knots,
    const float* __restrict__ coefs,
    const float* __restrict__ coefs2,
    float* __restrict__ out) {
    __shared__ float s_sx[ROWS_PER_BLOCK];

    const int tid = threadIdx.x;
    const int j   = blockIdx.x * COLS_PER_BLOCK + tid * 4;  // base column
    const int r0  = blockIdx.y * ROWS_PER_BLOCK;            // base row

    // Row spline values -> SMEM (threads 0..63).
    if (tid < ROWS_PER_BLOCK) {
        s_sx[tid] = spline_eval(__ldg(x + r0 + tid), knots, coefs);
    }

    // Column spline values for this thread's 4 columns (independent -> ILP).
    float4 tv = *reinterpret_cast<const float4*>(t + j);
    float4 s4;
    s4.x = spline_eval(tv.x, knots, coefs2);
    s4.y = spline_eval(tv.y, knots, coefs2);
    s4.z = spline_eval(tv.z, knots, coefs2);
    s4.w = spline_eval(tv.w, knots, coefs2);

    __syncthreads();

    // Store drain: 64 rows x 16B per thread, fully coalesced, streaming.
    float4* outp = reinterpret_cast<float4*>(out + (size_t)r0 * NT + j);
#pragma unroll 16
    for (int r = 0; r < ROWS_PER_BLOCK; r++) {
        float a = s_sx[r];
        float4 o;
        o.x = a * s4.x;
        o.y = a * s4.y;
        o.z = a * s4.z;
        o.w = a * s4.w;
        __stcs(outp, o);
        outp += NT / 4;
    }
}

extern "C" void kernel_launch(void* const* d_in, const int* in_sizes, int n_in,
                              void* d_out, int out_size) {
    const float* x      = (const float*)d_in[0];
    const float* t      = (const float*)d_in[1];
    const float* knots  = (const float*)d_in[2];
    const float* coefs  = (const float*)d_in[3];
    const float* coefs2 = (const float*)d_in[4];
    float* out = (float*)d_out;

    dim3 grid(NT / COLS_PER_BLOCK, NX / ROWS_PER_BLOCK);  // (8, 128)
    bspline_outer_fused<<<grid, TPB>>>(x, t, knots, coefs, coefs2, out);
}